// round 4
// baseline (speedup 1.0000x reference)
#include <cuda_runtime.h>
#include <cuda_bf16.h>

// NSLoss: loss = -(1/n) * sum_i [ log_sigmoid(<emb_i, W[label_i]>)
//                                 + sum_k log_sigmoid(-<emb_i, W[negs_ik]>) ]
// Inputs (metadata order): y_hat f32[N] (unused), emb f32[N,128],
// weights f32[1e6,128], label int32[N], negs int32[N,10]. Output: f32 scalar.
// (Reference uses int64 indices; harness dtype set is f32/i32/bf16 -> stored i32.)

#define D 128
#define NUM_SAMPLED 10
#define NROWS (NUM_SAMPLED + 1)   // 11 gathered rows per i
#define THREADS 256
#define WARPS_PER_BLOCK (THREADS / 32)
#define NUM_NODES 1000000

__device__ double g_acc;

__global__ void zero_acc_kernel() { g_acc = 0.0; }

__device__ __forceinline__ float log_sigmoid_f(float x) {
    // stable: min(x,0) - log1p(exp(-|x|))
    return fminf(x, 0.0f) - log1pf(__expf(-fabsf(x)));
}

__global__ __launch_bounds__(THREADS)
void nsloss_kernel(const float* __restrict__ emb,
                   const float* __restrict__ weights,
                   const int* __restrict__ label,
                   const int* __restrict__ negs,
                   int n) {
    const int lane = threadIdx.x & 31;
    const int warp_in_blk = threadIdx.x >> 5;
    const int i = blockIdx.x * WARPS_PER_BLOCK + warp_in_blk;

    float warp_partial = 0.0f;

    if (i < n) {
        // Coalesced emb load: 512B per warp, float4 per lane.
        const float4 e = reinterpret_cast<const float4*>(emb + (size_t)i * D)[lane];

        // Row indices: lane 0 -> label, lanes 1..10 -> negs. Broadcast by shuffle.
        int my_idx = 0;
        if (lane == 0)                my_idx = label[i];
        else if (lane <= NUM_SAMPLED) my_idx = negs[i * NUM_SAMPLED + (lane - 1)];
        // Defensive clamp: dtype mismatch shows up as rel_err, not a crash.
        my_idx = min(max(my_idx, 0), NUM_NODES - 1);

        // Prefetch all 11 weight rows (MLP=11 to cover DRAM latency).
        float4 w[NROWS];
        #pragma unroll
        for (int k = 0; k < NROWS; ++k) {
            int row = __shfl_sync(0xffffffffu, my_idx, k);
            w[k] = reinterpret_cast<const float4*>(weights + (size_t)row * D)[lane];
        }

        float acc = 0.0f;
        #pragma unroll
        for (int k = 0; k < NROWS; ++k) {
            float dot = e.x * w[k].x + e.y * w[k].y + e.z * w[k].z + e.w * w[k].w;
            #pragma unroll
            for (int off = 16; off > 0; off >>= 1)
                dot += __shfl_xor_sync(0xffffffffu, dot, off);
            // k==0: positive (score = +dot); k>0: negative (score = -dot)
            float s = (k == 0) ? dot : -dot;
            acc += log_sigmoid_f(s);
        }
        warp_partial = acc;   // identical on all lanes
    }

    __shared__ float warp_sums[WARPS_PER_BLOCK];
    if (lane == 0) warp_sums[warp_in_blk] = warp_partial;
    __syncthreads();

    if (threadIdx.x == 0) {
        float s = 0.0f;
        #pragma unroll
        for (int wi = 0; wi < WARPS_PER_BLOCK; ++wi) s += warp_sums[wi];
        atomicAdd(&g_acc, (double)s);
    }
}

__global__ void finalize_kernel(float* out, int n) {
    out[0] = (float)(-g_acc / (double)n);
}

extern "C" void kernel_launch(void* const* d_in, const int* in_sizes, int n_in,
                              void* d_out, int out_size) {
    const float* emb     = (const float*)d_in[1];
    const float* weights = (const float*)d_in[2];
    const int*   label   = (const int*)d_in[3];
    const int*   negs    = (const int*)d_in[4];
    float* out = (float*)d_out;

    const int n = in_sizes[0];              // N from y_hat length
    const int blocks = (n + WARPS_PER_BLOCK - 1) / WARPS_PER_BLOCK;

    zero_acc_kernel<<<1, 1>>>();
    nsloss_kernel<<<blocks, THREADS>>>(emb, weights, label, negs, n);
    finalize_kernel<<<1, 1>>>(out, n);
}

// round 5
// speedup vs baseline: 1.0218x; 1.0218x over previous
#include <cuda_runtime.h>
#include <cuda_bf16.h>

// NSLoss fused single-kernel: loss = -(1/n) * sum_i [ log_sigmoid(<emb_i, W[label_i]>)
//                                + sum_k log_sigmoid(-<emb_i, W[negs_ik]>) ]
// Inputs (metadata order): y_hat f32[N] (unused), emb f32[N,128],
// weights f32[1e6,128], label i32[N], negs i32[N,10]. Output: f32 scalar.
// Last arriving block finalizes output and resets accumulator state so the
// kernel is graph-replayable with no zero/finalize launches.

#define D 128
#define NUM_SAMPLED 10
#define NROWS (NUM_SAMPLED + 1)
#define THREADS 256
#define WARPS_PER_BLOCK (THREADS / 32)
#define NUM_NODES 1000000

__device__ double g_acc = 0.0;
__device__ unsigned int g_arrived = 0;

__device__ __forceinline__ float log_sigmoid_f(float x) {
    return fminf(x, 0.0f) - log1pf(__expf(-fabsf(x)));
}

__global__ __launch_bounds__(THREADS)
void nsloss_fused_kernel(const float* __restrict__ emb,
                         const float* __restrict__ weights,
                         const int* __restrict__ label,
                         const int* __restrict__ negs,
                         float* __restrict__ out,
                         int n) {
    const int lane = threadIdx.x & 31;
    const int warp_in_blk = threadIdx.x >> 5;
    const int i = blockIdx.x * WARPS_PER_BLOCK + warp_in_blk;

    float warp_partial = 0.0f;

    if (i < n) {
        // Coalesced emb load: 512B per warp, float4 per lane.
        const float4 e = reinterpret_cast<const float4*>(emb + (size_t)i * D)[lane];

        // Row indices: lane 0 -> label, lanes 1..10 -> negs. Broadcast by shuffle.
        int my_idx = 0;
        if (lane == 0)                my_idx = label[i];
        else if (lane <= NUM_SAMPLED) my_idx = negs[i * NUM_SAMPLED + (lane - 1)];
        my_idx = min(max(my_idx, 0), NUM_NODES - 1);

        // Prefetch all 11 weight rows (MLP=11 covers DRAM latency).
        float4 w[NROWS];
        #pragma unroll
        for (int k = 0; k < NROWS; ++k) {
            int row = __shfl_sync(0xffffffffu, my_idx, k);
            w[k] = reinterpret_cast<const float4*>(weights + (size_t)row * D)[lane];
        }

        float acc = 0.0f;
        #pragma unroll
        for (int k = 0; k < NROWS; ++k) {
            float dot = e.x * w[k].x + e.y * w[k].y + e.z * w[k].z + e.w * w[k].w;
            #pragma unroll
            for (int off = 16; off > 0; off >>= 1)
                dot += __shfl_xor_sync(0xffffffffu, dot, off);
            float s = (k == 0) ? dot : -dot;   // positive vs negative sample
            acc += log_sigmoid_f(s);
        }
        warp_partial = acc;   // identical on all lanes
    }

    // Block reduce (warp partials are lane-uniform; lane 0 contributes).
    __shared__ float warp_sums[WARPS_PER_BLOCK];
    __shared__ bool is_last;
    if (lane == 0) warp_sums[warp_in_blk] = warp_partial;
    __syncthreads();

    if (threadIdx.x == 0) {
        float s = 0.0f;
        #pragma unroll
        for (int wi = 0; wi < WARPS_PER_BLOCK; ++wi) s += warp_sums[wi];
        atomicAdd(&g_acc, (double)s);
        __threadfence();
        unsigned int prev = atomicAdd(&g_arrived, 1u);
        is_last = (prev == gridDim.x - 1);
    }
    __syncthreads();

    // Last block finalizes: write output, reset state for next graph replay.
    if (is_last && threadIdx.x == 0) {
        double total = g_acc;
        out[0] = (float)(-total / (double)n);
        g_acc = 0.0;
        g_arrived = 0u;
        __threadfence();
    }
}

extern "C" void kernel_launch(void* const* d_in, const int* in_sizes, int n_in,
                              void* d_out, int out_size) {
    const float* emb     = (const float*)d_in[1];
    const float* weights = (const float*)d_in[2];
    const int*   label   = (const int*)d_in[3];
    const int*   negs    = (const int*)d_in[4];
    float* out = (float*)d_out;

    const int n = in_sizes[0];              // N from y_hat length
    const int blocks = (n + WARPS_PER_BLOCK - 1) / WARPS_PER_BLOCK;

    nsloss_fused_kernel<<<blocks, THREADS>>>(emb, weights, label, negs, out, n);
}